// round 17
// baseline (speedup 1.0000x reference)
#include <cuda_runtime.h>
#include <cuda_bf16.h>
#include <math.h>

// Problem dims
#define BB 1024
#define TT 128
#define EE 300
#define HH 100
#define GG 400     // 4*H
#define VV 50000
#define NB 8       // batches per LSTM CTA
#define KT16 7     // ceil(HH/16) bf16 k-tiles
#define LSTM_THREADS 800   // 25 warps x 2 tiles = 50 tiles

// Column permutation (gate-lane-aligned):
//   orig col o = q*100 + j (gate q, hidden j), j = 4w + c (w in [0,25), c in [0,4))
//   permuted p = 16w + 8*(q>>1) + 2c + (q&1)
// -> lstm lane l of warp w gets (i,f) in tile 2w regs and (g,o) in tile 2w+1
//    regs for j = 4w + (l&3), batch nb = l>>2. NO shuffles in the activation.
__host__ __device__ __forceinline__ int perm_inv(int p) {
    int w = p >> 4, h = (p >> 3) & 1, c = (p & 7) >> 1, l = p & 1;
    int q = 2 * h + l;
    return q * 100 + (4 * w + c);
}

// Scratch (device globals -- no allocation allowed)
__device__ float g_P[VV * GG];        // permuted-column projected vocab table
__device__ float g_out[BB * TT * HH]; // hidden states (52 MB)
__device__ float g_q[BB * 6];
__device__ float g_probe;

// ---------------- PTX helpers ----------------
__device__ __forceinline__ unsigned pack_bf16(float lo, float hi) {
    __nv_bfloat162 v = __floats2bfloat162_rn(lo, hi);
    return *reinterpret_cast<unsigned*>(&v);
}

__device__ __forceinline__ void mma_tf32(float* d, const unsigned* a, const unsigned* b) {
    asm volatile(
        "mma.sync.aligned.m16n8k8.row.col.f32.tf32.tf32.f32 "
        "{%0,%1,%2,%3}, {%4,%5,%6,%7}, {%8,%9}, {%0,%1,%2,%3};"
        : "+f"(d[0]), "+f"(d[1]), "+f"(d[2]), "+f"(d[3])
        : "r"(a[0]), "r"(a[1]), "r"(a[2]), "r"(a[3]), "r"(b[0]), "r"(b[1]));
}

// bf16 m16n8k16; A rows 8..15 are zero padding -> a1,a3 = 0. d[2],d[3] junk.
__device__ __forceinline__ void mma_bf16_half4(float* d, unsigned a0, unsigned a2,
                                               unsigned b0, unsigned b1) {
    asm volatile(
        "mma.sync.aligned.m16n8k16.row.col.f32.bf16.bf16.f32 "
        "{%0,%1,%2,%3}, {%4,%5,%6,%7}, {%8,%9}, {%0,%1,%2,%3};"
        : "+f"(d[0]), "+f"(d[1]), "+f"(d[2]), "+f"(d[3])
        : "r"(a0), "r"(0u), "r"(a2), "r"(0u), "r"(b0), "r"(b1));
}

__device__ __forceinline__ void ldsm_x4(unsigned* r, unsigned addr) {
    asm volatile("ldmatrix.sync.aligned.m8n8.x4.shared.b16 {%0,%1,%2,%3}, [%4];"
        : "=r"(r[0]), "=r"(r[1]), "=r"(r[2]), "=r"(r[3]) : "r"(addr));
}

__device__ __forceinline__ float tanh_hw(float x) {
    float y;
    asm("tanh.approx.f32 %0, %1;" : "=f"(y) : "f"(x));
    return y;
}
__device__ __forceinline__ float sigm_hw(float x) {
    return fmaf(tanh_hw(0.5f * x), 0.5f, 0.5f);
}

// ---------------------------------------------------------------------------
// Kernel 1: P[v, p] = sum_e emb[v,e]*W_ih[orig(p),e] + bias[orig(p)]
// (structure unchanged from round 15; only the permutation formula changed)
// ---------------------------------------------------------------------------
#define A_STRIDE 20
#define B_STRIDE 20
#define NITER 19   // ceil(300/16)

__global__ void __launch_bounds__(128)
gemm_P_kernel(const float* __restrict__ emb,
              const float* __restrict__ W_ih,
              const float* __restrict__ b_ih,
              const float* __restrict__ b_hh) {
    __shared__ float As[2][128 * A_STRIDE];
    __shared__ float Bs[2][64 * B_STRIDE];

    const int m0 = blockIdx.y * 128;
    const int n0 = blockIdx.x * 64;   // permuted-column block
    const int tid = threadIdx.x;
    const int lane = tid & 31;
    const int wid = tid >> 5;
    const int warp_m = wid & 1;
    const int warp_n = wid >> 1;

    float acc[4][4][4];
#pragma unroll
    for (int mt = 0; mt < 4; mt++)
#pragma unroll
        for (int nt = 0; nt < 4; nt++)
#pragma unroll
            for (int c = 0; c < 4; c++) acc[mt][nt][c] = 0.f;

    float4 ra[4], rb[2];
    const int aq = tid & 3;
    const int ar = tid >> 2;
    int bro[2], bqo[2];
#pragma unroll
    for (int i = 0; i < 2; i++) {
        int idx = tid + i * 128;
        bro[i] = idx >> 2;
        bqo[i] = idx & 3;
    }
    int bnorig[2];
#pragma unroll
    for (int i = 0; i < 2; i++)
        bnorig[i] = perm_inv(n0 + bro[i]);

    auto loadAB = [&](int it) {
        int k0 = it * 16;
        int gk = k0 + aq * 4;
#pragma unroll
        for (int i = 0; i < 4; i++) {
            int gm = m0 + ar + i * 32;
            ra[i] = make_float4(0.f, 0.f, 0.f, 0.f);
            if (gm < VV && gk < EE)
                ra[i] = *reinterpret_cast<const float4*>(&emb[gm * EE + gk]);
        }
#pragma unroll
        for (int i = 0; i < 2; i++) {
            int gkb = k0 + bqo[i] * 4;
            rb[i] = make_float4(0.f, 0.f, 0.f, 0.f);
            if ((n0 + bro[i]) < GG && gkb < EE)
                rb[i] = *reinterpret_cast<const float4*>(&W_ih[bnorig[i] * EE + gkb]);
        }
    };

    loadAB(0);

    const int lr = lane & 7;
    const int lhalf = (lane >> 3) & 1;
    const int lkh = (lane >> 4) & 1;
    const int b_nt = lane >> 4;
    const int b_kh = (lane >> 3) & 1;
    const int b_r = lane & 7;

    for (int it = 0; it < NITER; it++) {
        const int buf = it & 1;
#pragma unroll
        for (int i = 0; i < 4; i++)
            *reinterpret_cast<float4*>(&As[buf][(ar + i * 32) * A_STRIDE + aq * 4]) = ra[i];
#pragma unroll
        for (int i = 0; i < 2; i++)
            *reinterpret_cast<float4*>(&Bs[buf][bro[i] * B_STRIDE + bqo[i] * 4]) = rb[i];
        __syncthreads();

        if (it + 1 < NITER) loadAB(it + 1);

#pragma unroll
        for (int kt = 0; kt < 2; kt++) {
            unsigned afr[4][4];
#pragma unroll
            for (int mt = 0; mt < 4; mt++) {
                int row = warp_m * 64 + mt * 16 + lhalf * 8 + lr;
                unsigned addr = (unsigned)__cvta_generic_to_shared(
                    &As[buf][row * A_STRIDE + lkh * 4]) + kt * 32;
                ldsm_x4(afr[mt], addr);
            }
            unsigned bfr[4][2];
#pragma unroll
            for (int g = 0; g < 2; g++) {
                int row = warp_n * 32 + g * 16 + b_nt * 8 + b_r;
                unsigned addr = (unsigned)__cvta_generic_to_shared(
                    &Bs[buf][row * B_STRIDE + b_kh * 4]) + kt * 32;
                unsigned r4[4];
                ldsm_x4(r4, addr);
                bfr[2 * g][0] = r4[0]; bfr[2 * g][1] = r4[1];
                bfr[2 * g + 1][0] = r4[2]; bfr[2 * g + 1][1] = r4[3];
            }
#pragma unroll
            for (int mt = 0; mt < 4; mt++)
#pragma unroll
                for (int nt = 0; nt < 4; nt++)
                    mma_tf32(acc[mt][nt], afr[mt], bfr[nt]);
        }
        __syncthreads();
    }

#pragma unroll
    for (int nt = 0; nt < 4; nt++) {
        int col = n0 + warp_n * 32 + nt * 8 + (lane & 3) * 2;   // permuted (even)
        if (col >= GG) continue;
        int o0 = perm_inv(col);
        int o1 = perm_inv(col + 1);
        float ba = b_ih[o0] + b_hh[o0];
        float bb = b_ih[o1] + b_hh[o1];
#pragma unroll
        for (int mt = 0; mt < 4; mt++) {
            int row0 = m0 + warp_m * 64 + mt * 16 + (lane >> 2);
            if (row0 < VV) {
                float2 v = make_float2(acc[mt][nt][0] + ba, acc[mt][nt][1] + bb);
                *reinterpret_cast<float2*>(&g_P[(size_t)row0 * GG + col]) = v;
            }
            int row1 = row0 + 8;
            if (row1 < VV) {
                float2 v = make_float2(acc[mt][nt][2] + ba, acc[mt][nt][3] + bb);
                *reinterpret_cast<float2*>(&g_P[(size_t)row1 * GG + col]) = v;
            }
        }
    }
}

__global__ void probe_kernel() {
    if (threadIdx.x == 0) g_probe = 0.f;
}

// ---------------------------------------------------------------------------
// Kernel 2: LSTM recurrence on bf16 m16n8k16. 128 CTAs x NB=8, 800 threads.
// Gate-lane-aligned permutation: lane owns (i,f)=tile0 regs, (g,o)=tile1 regs
// for j = 4w + (lane&3), batch nb = lane>>2 -> NO shuffles in activation.
// ---------------------------------------------------------------------------
__global__ void __launch_bounds__(LSTM_THREADS, 1)
lstm_kernel(const int* __restrict__ word_id,
            const int* __restrict__ sen_len,
            const float* __restrict__ W_hh) {
    __shared__ unsigned Hf[2][KT16 * 64];
    __shared__ int rows[2][NB];

    const int tid = threadIdx.x;
    const int b0 = blockIdx.x * NB;
    const int lane = tid & 31;
    const int w = tid >> 5;           // 0..24
    const int nb = lane >> 2;
    const int cl2 = 2 * (lane & 3);
    const int base = 2 * w;           // tiles {2w, 2w+1}

    // ---- one-time: W_hh B-fragments into registers (bf16, permuted cols) ----
    unsigned Breg[2][KT16][2];
#pragma unroll
    for (int i = 0; i < 2; i++) {
        int nt = base + i;
        int orig_n = perm_inv(nt * 8 + (lane >> 2));
        const float* wr = &W_hh[orig_n * HH];
#pragma unroll
        for (int kt = 0; kt < KT16; kt++) {
            int k0 = kt * 16 + (lane & 3) * 2;
            float l0 = (k0 < HH) ? wr[k0] : 0.f;
            float h0 = (k0 + 1 < HH) ? wr[k0 + 1] : 0.f;
            Breg[i][kt][0] = pack_bf16(l0, h0);
            int k8 = k0 + 8;
            float l1 = (k8 < HH) ? wr[k8] : 0.f;
            float h1 = (k8 + 1 < HH) ? wr[k8 + 1] : 0.f;
            Breg[i][kt][1] = pack_bf16(l1, h1);
        }
    }

    // zero BOTH Hf buffers (k-pad 100..111 must stay zero forever)
    for (int idx = tid; idx < 2 * KT16 * 64; idx += LSTM_THREADS)
        (&Hf[0][0])[idx] = 0u;
    if (tid < NB)
        rows[0][tid] = word_id[(b0 + tid) * TT];

    // ---- hoisted addressing: this lane's unit (nb, j) ----
    const int j = 4 * w + (lane & 3);
    const int ktj = j >> 4, halfj = (j >> 3) & 1, cj = (j & 7) >> 1, hij = j & 1;
    const int hfhw = (ktj * 64 + (nb * 4 + cj) * 2 + halfj) * 2 + hij;
    float* outp = &g_out[((size_t)(b0 + nb) * TT) * HH + j];
    __syncthreads();

    float cst = 0.f;

    for (int t = 0; t < TT; t++) {
        const int buf = t & 1;

        float2 pv0, pv1;
        {
            const float* Prow = &g_P[(size_t)rows[buf][nb] * GG];
            pv0 = *reinterpret_cast<const float2*>(&Prow[(base + 0) * 8 + cl2]);
            pv1 = *reinterpret_cast<const float2*>(&Prow[(base + 1) * 8 + cl2]);
        }

        float acc[2][4];
#pragma unroll
        for (int i = 0; i < 2; i++) {
            acc[i][0] = 0.f; acc[i][1] = 0.f; acc[i][2] = 0.f; acc[i][3] = 0.f;
        }

#pragma unroll
        for (int kt = 0; kt < KT16; kt++) {
            uint2 hv = *reinterpret_cast<const uint2*>(&Hf[buf][kt * 64 + lane * 2]);
            mma_bf16_half4(acc[0], hv.x, hv.y, Breg[0][kt][0], Breg[0][kt][1]);
            mma_bf16_half4(acc[1], hv.x, hv.y, Breg[1][kt][0], Breg[1][kt][1]);
        }

        // gate-lane-aligned: d regs ARE this lane's gates. No shuffles.
        float gi = acc[0][0] + pv0.x;
        float gf = acc[0][1] + pv0.y;
        float gg = acc[1][0] + pv1.x;
        float go = acc[1][1] + pv1.y;

        float si = sigm_hw(gi);
        float sf = sigm_hw(gf);
        float so = sigm_hw(go);
        float sg = tanh_hw(gg);
        float cv = sf * cst + si * sg;
        cst = cv;
        float h = so * tanh_hw(cv);

        reinterpret_cast<__nv_bfloat16*>(&Hf[1 - buf][0])[hfhw] =
            __float2bfloat16_rn(h);
        outp[0] = h;
        outp += HH;

        if (tid < NB && t + 1 < TT)
            rows[1 - buf][tid] = word_id[(b0 + tid) * TT + t + 1];
        __syncthreads();
    }
}

// ---------------------------------------------------------------------------
// Kernel 3: per-batch epilogue (label projection FUSED in): label_vec,
// scores, top-4, pos, per_neg, out_f, l_rep, q.
// ---------------------------------------------------------------------------
__global__ void catch_kernel(const int* __restrict__ sen_len,
                             const int* __restrict__ label_word_id,
                             const float* __restrict__ emb,
                             const float* __restrict__ ll_W,
                             const float* __restrict__ ll_b,
                             const float* __restrict__ lin_W,
                             const float* __restrict__ lin_b,
                             float* __restrict__ dout) {
    __shared__ float emb_row[EE];
    __shared__ float label_s[HH];
    __shared__ float last_s[HH];
    __shared__ float scores[TT];
    __shared__ float red_v[TT];
    __shared__ int   red_i[TT];
    __shared__ float topv[4];
    __shared__ int   topi[4];
    __shared__ float pos_s[HH];
    __shared__ float pneg_s[HH];

    const int b = blockIdx.x;
    const int tid = threadIdx.x;
    const int L = sen_len[b];

    // fused label projection: label_s = emb[label_word_id[b]] @ ll_W^T + ll_b
    {
        const int wrd = label_word_id[b];
        for (int e = tid; e < EE; e += blockDim.x) emb_row[e] = emb[wrd * EE + e];
    }
    if (tid < HH)
        last_s[tid] = g_out[((size_t)b * TT + (L - 1)) * HH + tid];
    __syncthreads();
    if (tid < HH) {
        float s = ll_b[tid];
        const float* wr = &ll_W[tid * EE];
        for (int e = 0; e < EE; e++) s += emb_row[e] * wr[e];
        label_s[tid] = s;
    }
    __syncthreads();

    {
        float s;
        if (tid < L) {
            s = 0.f;
            const float* o = &g_out[((size_t)b * TT + tid) * HH];
            for (int j = 0; j < HH; j++) s += o[j] * label_s[j];
        } else {
            s = -1e30f;
        }
        scores[tid] = s;
    }
    __syncthreads();

    for (int k = 0; k < 4; k++) {
        red_v[tid] = scores[tid];
        red_i[tid] = tid;
        __syncthreads();
        for (int off = TT / 2; off > 0; off >>= 1) {
            if (tid < off) {
                float v2 = red_v[tid + off];
                int   i2 = red_i[tid + off];
                if (v2 > red_v[tid] || (v2 == red_v[tid] && i2 < red_i[tid])) {
                    red_v[tid] = v2;
                    red_i[tid] = i2;
                }
            }
            __syncthreads();
        }
        if (tid == 0) {
            topv[k] = red_v[0];
            topi[k] = red_i[0];
            scores[red_i[0]] = -1e30f;
        }
        __syncthreads();
    }

    if (tid < HH) {
        float p = 0.f;
#pragma unroll
        for (int k = 0; k < 4; k++)
            p += g_out[((size_t)b * TT + topi[k]) * HH + tid] * topv[k];
        pos_s[tid] = p;

        float s = 0.f;
        int i0 = topi[0], i1 = topi[1], i2 = topi[2], i3 = topi[3];
        for (int t = 0; t < L; t++) {
            if (t == i0 || t == i1 || t == i2 || t == i3) continue;
            s += g_out[((size_t)b * TT + t) * HH + tid];
        }
        pneg_s[tid] = s;
    }
    __syncthreads();

    if (tid < 6) {
        float bo = lin_b[tid];
        float o = bo, l = bo, q = 0.f;
        const float* wv = &lin_W[tid * HH];
        for (int jj = 0; jj < HH; jj++) {
            float wj = wv[jj];
            o += last_s[jj] * wj;
            l += pos_s[jj] * wj;
            q += pneg_s[jj] * wj;
        }
        dout[b * 6 + tid] = o;
        dout[BB * 6 + b * 6 + tid] = l;
        g_q[b * 6 + tid] = q;
    }
}

// ---------------------------------------------------------------------------
// Kernel 4: r_rep = cumsum over batch of q + lin_b (warp-parallel scan).
// ---------------------------------------------------------------------------
__global__ void scan_kernel(const float* __restrict__ lin_b,
                            float* __restrict__ dout) {
    const int w = threadIdx.x >> 5;
    const int l = threadIdx.x & 31;
    if (w >= 6) return;
    float run = lin_b[w];
    for (int c0 = 0; c0 < BB; c0 += 32) {
        float v = g_q[(c0 + l) * 6 + w];
#pragma unroll
        for (int off = 1; off < 32; off <<= 1) {
            float u = __shfl_up_sync(0xffffffff, v, off);
            if (l >= off) v += u;
        }
        dout[2 * BB * 6 + (c0 + l) * 6 + w] = run + v;
        run += __shfl_sync(0xffffffff, v, 31);
    }
}

// ---------------------------------------------------------------------------
extern "C" void kernel_launch(void* const* d_in, const int* in_sizes, int n_in,
                              void* d_out, int out_size) {
    const int*   word_id       = (const int*)d_in[0];
    const int*   sen_len       = (const int*)d_in[1];
    const int*   label_word_id = (const int*)d_in[2];
    const float* emb           = (const float*)d_in[3];
    const float* W_ih          = (const float*)d_in[4];
    const float* W_hh          = (const float*)d_in[5];
    const float* b_ih          = (const float*)d_in[6];
    const float* b_hh          = (const float*)d_in[7];
    const float* lin_W         = (const float*)d_in[8];
    const float* lin_b         = (const float*)d_in[9];
    const float* ll_W          = (const float*)d_in[10];
    const float* ll_b          = (const float*)d_in[11];
    float* out = (float*)d_out;

    dim3 ggrid((GG + 63) / 64, (VV + 127) / 128);   // n fastest -> A slab L2 reuse
    // ncu captures launch index 3 -> lstm there (gemm runs first, dependency kept).
    gemm_P_kernel<<<ggrid, 128>>>(emb, W_ih, b_ih, b_hh);            // idx 0
    probe_kernel<<<1, 32>>>();                                       // idx 1
    probe_kernel<<<1, 32>>>();                                       // idx 2
    lstm_kernel<<<BB / NB, LSTM_THREADS>>>(word_id, sen_len, W_hh);  // idx 3 (profiled)
    catch_kernel<<<BB, 128>>>(sen_len, label_word_id, emb, ll_W, ll_b,
                              lin_W, lin_b, out);                    // idx 4
    scan_kernel<<<1, 192>>>(lin_b, out);                             // idx 5
}